// round 6
// baseline (speedup 1.0000x reference)
#include <cuda_runtime.h>

#define DINL __device__ __forceinline__
typedef unsigned long long ull;

constexpr int BATCH = 8192;

// channel-last activations: (n, pix, ci), except y4 which is (n, co, pix)
__device__ short g_y1[(size_t)BATCH * 345 * 12];
__device__ short g_y2[(size_t)BATCH * 77 * 24];
__device__ short g_y3[(size_t)BATCH * 15 * 48];
__device__ short g_y4[(size_t)BATCH * 192];

__device__ ull g_sum[512];   // layer l at offset l*128
__device__ ull g_sq[512];

__device__ unsigned g_wp1[12 * 5 * 1];
__device__ unsigned g_wp2[24 * 5 * 2];
__device__ unsigned g_wp3[48 * 5 * 4];
__device__ unsigned g_wp4[96 * 5 * 8];
__device__ unsigned g_wlp[360 * 6];

template <int WIDTH>
DINL unsigned wmask_w(int j) {
    int rem = WIDTH - 32 * j;
    return (rem >= 32) ? 0xFFFFFFFFu : ((1u << rem) - 1u);
}

DINL float2 bn_coef(int layer, int c, double invN,
                    const float* __restrict__ g, const float* __restrict__ be) {
    long long S = (long long)g_sum[layer * 128 + c];
    long long Q = (long long)g_sq[layer * 128 + c];
    double m = (double)S * invN;
    double v = (double)Q * invN - m * m;
    double a = (double)g[c] / sqrt(v + 1e-5);
    return make_float2((float)a, (float)((double)be[c] - m * a));
}

// ---------------------------------------------------------------------------
// Prep
// ---------------------------------------------------------------------------
template <int CI, int CO>
DINL void pack_w(const float* __restrict__ w, unsigned* __restrict__ outw,
                 int gtid, int gsz) {
    constexpr int NW = (5 * CI + 31) / 32;
    const int tot = CO * 5 * NW;
    for (int u = gtid; u < tot; u += gsz) {
        int co = u / (5 * NW);
        int kh = (u / NW) % 5;
        int j = u % NW;
        unsigned wd = 0;
        for (int b = 0; b < 32; b++) {
            int t = 32 * j + b;
            if (t < 5 * CI) {
                int kw = t / CI, ci = t % CI;
                if (w[((co * CI + ci) * 5 + kh) * 5 + kw] > 0.0f) wd |= 1u << b;
            }
        }
        outw[u] = wd;
    }
}

__global__ void prep_kernel(const float* __restrict__ w1, const float* __restrict__ w2,
                            const float* __restrict__ w3, const float* __restrict__ w4,
                            const float* __restrict__ wl) {
    int gtid = blockIdx.x * blockDim.x + threadIdx.x;
    int gsz = gridDim.x * blockDim.x;
    for (int i = gtid; i < 512; i += gsz) { g_sum[i] = 0ull; g_sq[i] = 0ull; }
    pack_w<6, 12>(w1, g_wp1, gtid, gsz);
    pack_w<12, 24>(w2, g_wp2, gtid, gsz);
    pack_w<24, 48>(w3, g_wp3, gtid, gsz);
    pack_w<48, 96>(w4, g_wp4, gtid, gsz);
    for (int u = gtid; u < 360 * 6; u += gsz) {
        int o = u / 6, j = u % 6;
        unsigned wd = 0;
        for (int b = 0; b < 32; b++)
            if (wl[o * 192 + 32 * j + b] > 0.0f) wd |= 1u << b;
        g_wlp[u] = wd;
    }
}

// ---------------------------------------------------------------------------
// BN stats: per-channel integer sum / sumsq over a y buffer.
// blockDim=192 so channel assignment per thread is loop-invariant.
// ---------------------------------------------------------------------------
template <int LAYER, int CO, bool PAIRSAME>
__global__ void __launch_bounds__(192) stats_kernel(int npairs) {
    const short* y;
    if constexpr (LAYER == 1) y = g_y1;
    else if constexpr (LAYER == 2) y = g_y2;
    else if constexpr (LAYER == 3) y = g_y3;
    else y = g_y4;

    __shared__ ull s_sum[CO], s_sq[CO];
    const int tid = threadIdx.x;
    for (int i = tid; i < CO; i += 192) { s_sum[i] = 0ull; s_sq[i] = 0ull; }
    __syncthreads();

    const int gtid = blockIdx.x * 192 + tid;
    const int S = gridDim.x * 192;
    const unsigned* yp = (const unsigned*)y;
    int sum0 = 0, sq0 = 0, sum1 = 0, sq1 = 0;
    for (int p = gtid; p < npairs; p += S) {
        unsigned u = yp[p];
        int a = (int)(short)(u & 0xFFFFu);
        int b = (int)(short)(u >> 16);
        if constexpr (PAIRSAME) {
            sum0 += a + b; sq0 += a * a + b * b;
        } else {
            sum0 += a; sq0 += a * a;
            sum1 += b; sq1 += b * b;
        }
    }
    if constexpr (PAIRSAME) {
        int c0 = gtid % CO;
        atomicAdd(&s_sum[c0], (ull)(long long)sum0);
        atomicAdd(&s_sq[c0], (ull)(long long)sq0);
    } else {
        int c0 = (2 * gtid) % CO;
        atomicAdd(&s_sum[c0], (ull)(long long)sum0);
        atomicAdd(&s_sq[c0], (ull)(long long)sq0);
        atomicAdd(&s_sum[c0 + 1], (ull)(long long)sum1);
        atomicAdd(&s_sq[c0 + 1], (ull)(long long)sq1);
    }
    __syncthreads();
    for (int c = tid; c < CO; c += 192) {
        atomicAdd(&g_sum[(LAYER - 1) * 128 + c], s_sum[c]);
        atomicAdd(&g_sq[(LAYER - 1) * 128 + c], s_sq[c]);
    }
}

// ---------------------------------------------------------------------------
// Layer 1: float input, sign in {-1,+1}, padding via mask popcount.
// ---------------------------------------------------------------------------
__global__ void __launch_bounds__(256) conv1_kernel(const float* __restrict__ x) {
    constexpr int CI = 6, HI = 32, WI = 48, CO = 12, HO = 15, WO = 23;
    constexpr int PIXI = HI * WI, NELEM = CI * PIXI, PIXO = HO * WO;
    constexpr int ROWBITS = (WI + 2) * CI;       // 300
    constexpr int ROWW = (ROWBITS + 31) / 32;    // 10
    constexpr int RWA = ROWW + 2;                // 12
    constexpr int PITCH = 320;
    constexpr int IMGS = 2;
    constexpr int NTASK = IMGS * PIXO;           // 690
    constexpr unsigned MASK30 = (1u << 30) - 1u;

    __shared__ unsigned char s_bits[IMGS * HI * PITCH];   // 20480
    __shared__ unsigned s_rows[IMGS * HI * RWA];          // 3072
    __shared__ unsigned s_wp[CO * 5];
    __shared__ unsigned s_mrow[RWA];

    const int tid = threadIdx.x;
    const int n0 = blockIdx.x * IMGS;

    for (int i = tid; i < CO * 5; i += 256) s_wp[i] = g_wp1[i];
    for (int i = tid; i < RWA; i += 256) {
        unsigned w = 0;
        for (int b = 0; b < 32; b++) {
            int t = 32 * i + b;
            int p = t / CI;
            if (t < ROWBITS && p >= 1 && p <= WI) w |= 1u << b;
        }
        s_mrow[i] = w;
    }
    for (int i = tid; i < IMGS * HI * RWA; i += 256) s_rows[i] = 0;
    {
        uint4 z = make_uint4(0, 0, 0, 0);
        uint4* p = (uint4*)s_bits;
        for (int i = tid; i < IMGS * HI * PITCH / 16; i += 256) p[i] = z;
    }
    __syncthreads();

    // stage: float4 -> {0,1} bytes, channel-last with 6B pad at row start
    const float4* xp4 = (const float4*)(x + (size_t)n0 * NELEM);
    for (int u = tid; u < IMGS * NELEM / 4; u += 256) {
        float4 v = xp4[u];
        int e = 4 * u;
        int m = e / NELEM, er = e % NELEM;
        int ci = er / PIXI, pr = er % PIXI;
        int ih = pr / WI, iw = pr % WI;
        unsigned char* bp = &s_bits[(m * HI + ih) * PITCH + 6 + iw * CI + ci];
        bp[0]      = (unsigned char)(v.x > 0.0f);
        bp[CI]     = (unsigned char)(v.y > 0.0f);
        bp[2 * CI] = (unsigned char)(v.z > 0.0f);
        bp[3 * CI] = (unsigned char)(v.w > 0.0f);
    }
    __syncthreads();

    // pack: 32 bytes -> 32 bits via nibble multiply trick
    for (int u = tid; u < IMGS * HI * ROWW; u += 256) {
        int row = u / ROWW, j = u % ROWW;
        const uint4* bw = (const uint4*)&s_bits[row * PITCH + 32 * j];
        uint4 a = bw[0], b = bw[1];
        unsigned w = 0;
        w |= ((a.x * 0x01020408u) >> 24);
        w |= ((a.y * 0x01020408u) >> 24) << 4;
        w |= ((a.z * 0x01020408u) >> 24) << 8;
        w |= ((a.w * 0x01020408u) >> 24) << 12;
        w |= ((b.x * 0x01020408u) >> 24) << 16;
        w |= ((b.y * 0x01020408u) >> 24) << 20;
        w |= ((b.z * 0x01020408u) >> 24) << 24;
        w |= ((b.w * 0x01020408u) >> 24) << 28;
        s_rows[row * RWA + j] = w;
    }
    __syncthreads();

    for (int t = tid; t < NTASK; t += 256) {
        int m = t / PIXO, pix = t % PIXO;
        int oh = pix / WO, ow = pix % WO;
        int s = 2 * ow * CI, wofs = s >> 5, sh = s & 31;

        unsigned aw[5], mw[5];
        int popA = 0;
#pragma unroll
        for (int kh = 0; kh < 5; kh++) {
            int ih = 2 * oh - 1 + kh;
            bool v = (ih >= 0 && ih < HI);
            const unsigned* rw = &s_rows[(m * HI + (v ? ih : 0)) * RWA + wofs];
            aw[kh] = __funnelshift_r(rw[0], rw[1], sh) & MASK30;
            unsigned mm = __funnelshift_r(s_mrow[wofs], s_mrow[wofs + 1], sh) & MASK30;
            mw[kh] = v ? mm : 0u;
            popA += __popc(mw[kh]);
        }
        unsigned* dst = (unsigned*)(g_y1 + ((size_t)(n0 + m) * PIXO + pix) * CO);
#pragma unroll
        for (int cp = 0; cp < CO / 2; cp++) {
            const unsigned* w0 = &s_wp[(2 * cp) * 5];
            const unsigned* w1 = &s_wp[(2 * cp + 1) * 5];
            int a0 = 0, a1 = 0;
#pragma unroll
            for (int kh = 0; kh < 5; kh++) {
                a0 += __popc(mw[kh] & ~(aw[kh] ^ w0[kh]));
                a1 += __popc(mw[kh] & ~(aw[kh] ^ w1[kh]));
            }
            int d0 = 2 * a0 - popA, d1 = 2 * a1 - popA;
            dst[cp] = ((unsigned)d0 & 0xFFFFu) | ((unsigned)d1 << 16);
        }
    }
}

// ---------------------------------------------------------------------------
// Layers 2-4: pairwise channel compute + immediate 32-bit store (low regs).
// ---------------------------------------------------------------------------
template <int LAYER, int CI, int HI, int WI, int CO, int HO, int WO,
          int IMGS, int COSPLIT, bool COMAJOR>
__global__ void __launch_bounds__(256) conv_rest(const float* __restrict__ gprev,
                                                 const float* __restrict__ beprev,
                                                 double invN) {
    constexpr int PIXI = HI * WI, PIXO = HO * WO;
    constexpr int ROWBITS = (WI + 2) * CI;
    constexpr int ROWW = (ROWBITS + 31) / 32;
    constexpr int NW = (5 * CI + 31) / 32;
    constexpr int RWA = ROWW + NW + 1;
    constexpr int COQ = CO / COSPLIT;
    constexpr int NTASK = IMGS * PIXO * COSPLIT;
    constexpr int WIDTH = 5 * CI;
    constexpr int CREP = CI + 32;

    __shared__ unsigned s_rows[IMGS * HI * RWA];
    __shared__ unsigned s_wp[CO * 5 * NW];
    __shared__ float2 s_crep[CREP];

    const int tid = threadIdx.x;
    const int n0 = blockIdx.x * IMGS;

    const short* yin = nullptr;
    short* yout = nullptr;
    const unsigned* wpg = nullptr;
    if constexpr (LAYER == 2) { yin = g_y1; yout = g_y2; wpg = g_wp2; }
    if constexpr (LAYER == 3) { yin = g_y2; yout = g_y3; wpg = g_wp3; }
    if constexpr (LAYER == 4) { yin = g_y3; yout = g_y4; wpg = g_wp4; }

    for (int i = tid; i < CO * 5 * NW; i += 256) s_wp[i] = wpg[i];
    for (int i = tid; i < IMGS * HI * RWA; i += 256) s_rows[i] = 0;
    if (tid < CI) {
        float2 cf = bn_coef(LAYER - 2, tid, invN, gprev, beprev);
        for (int r = tid; r < CREP; r += CI) s_crep[r] = cf;
    }
    __syncthreads();

    // pack: binarize directly from channel-last gmem (contiguous 32 shorts/word)
    for (int u = tid; u < IMGS * HI * ROWW; u += 256) {
        int row = u / ROWW, j = u % ROWW;
        int m = row / HI, r = row % HI;
        const short* yrow = yin + ((size_t)(n0 + m) * PIXI + r * WI) * CI;
        int mo0 = 32 * j - CI;
        int ci0 = (32 * j) % CI;
        unsigned w = 0;
        if (mo0 >= 0 && mo0 + 32 <= WI * CI) {
            const uint2* p = (const uint2*)(yrow + mo0);
            uint2 q[8];
#pragma unroll
            for (int k2 = 0; k2 < 8; k2++) q[k2] = p[k2];
#pragma unroll
            for (int b = 0; b < 32; b++) {
                unsigned raw = (b & 2) ? q[b >> 2].y : q[b >> 2].x;
                short sv = (short)(raw >> ((b & 1) * 16));
                float2 c = s_crep[ci0 + b];
                if (fmaf(c.x, (float)sv, c.y) > 0.0f) w |= 1u << b;
            }
        } else {
#pragma unroll
            for (int b = 0; b < 32; b++) {
                int mo = mo0 + b;
                if (mo >= 0 && mo < WI * CI) {
                    float2 c = s_crep[ci0 + b];
                    short sv = yrow[mo];
                    if (fmaf(c.x, (float)sv, c.y) > 0.0f) w |= 1u << b;
                }
            }
        }
        s_rows[row * RWA + j] = w;
    }
    __syncthreads();

    for (int t = tid; t < NTASK; t += 256) {
        int coq, pt;
        if constexpr (COSPLIT > 1) {
            coq = t / (IMGS * PIXO);
            pt = t % (IMGS * PIXO);
        } else { coq = 0; pt = t; }
        int m = pt / PIXO, pix = pt % PIXO;
        int oh = pix / WO, ow = pix % WO;
        int s = 2 * ow * CI, wofs = s >> 5, sh = s & 31;

        unsigned aw[5][NW];
        int popA = 0;
#pragma unroll
        for (int kh = 0; kh < 5; kh++) {
            int ih = 2 * oh - 1 + kh;
            bool v = (ih >= 0 && ih < HI);
            const unsigned* rw = &s_rows[(m * HI + (v ? ih : 0)) * RWA + wofs];
#pragma unroll
            for (int j = 0; j < NW; j++) {
                unsigned msk = wmask_w<WIDTH>(j);
                unsigned win = __funnelshift_r(rw[j], rw[j + 1], sh) & msk;
                aw[kh][j] = v ? win : 0u;
                popA += __popc(aw[kh][j]);
            }
        }
        if constexpr (COMAJOR) {
            short* dst = yout + (size_t)(n0 + m) * (CO * PIXO) + pix;
#pragma unroll
            for (int cp = 0; cp < COQ; cp++) {
                int co = coq * COQ + cp;
                const unsigned* wpc = &s_wp[co * 5 * NW];
                int acc = 0;
#pragma unroll
                for (int kh = 0; kh < 5; kh++)
#pragma unroll
                    for (int j = 0; j < NW; j++)
                        acc += __popc(aw[kh][j] & wpc[kh * NW + j]);
                dst[co * PIXO] = (short)(2 * acc - popA);
            }
        } else {
            unsigned* dst = (unsigned*)(yout + ((size_t)(n0 + m) * PIXO + pix) * CO);
#pragma unroll
            for (int cp = 0; cp < COQ / 2; cp++) {
                int co = coq * COQ + 2 * cp;
                const unsigned* w0 = &s_wp[co * 5 * NW];
                const unsigned* w1 = &s_wp[(co + 1) * 5 * NW];
                int a0 = 0, a1 = 0;
#pragma unroll
                for (int kh = 0; kh < 5; kh++)
#pragma unroll
                    for (int j = 0; j < NW; j++) {
                        a0 += __popc(aw[kh][j] & w0[kh * NW + j]);
                        a1 += __popc(aw[kh][j] & w1[kh * NW + j]);
                    }
                int d0 = 2 * a0 - popA, d1 = 2 * a1 - popA;
                dst[coq * COQ / 2 + cp] = ((unsigned)d0 & 0xFFFFu) | ((unsigned)d1 << 16);
            }
        }
    }
}

// ---------------------------------------------------------------------------
// Final binary linear: weights register-resident, rows broadcast from smem.
// ---------------------------------------------------------------------------
__global__ void __launch_bounds__(256) linear_kernel(const float* __restrict__ g4,
                                                     const float* __restrict__ be4,
                                                     const float* __restrict__ bl,
                                                     float* __restrict__ out) {
    __shared__ unsigned s_w[360 * 6];
    __shared__ unsigned s_b[32 * 6];
    __shared__ int s_pop[32];
    __shared__ float s_bl[360];
    __shared__ float2 s_coef[96];

    int tid = threadIdx.x;
    for (int i = tid; i < 360 * 6; i += 256) s_w[i] = g_wlp[i];
    for (int i = tid; i < 360; i += 256) s_bl[i] = bl[i];
    if (tid < 96) s_coef[tid] = bn_coef(3, tid, 1.0 / ((double)BATCH * 2), g4, be4);
    __syncthreads();

    int n0 = blockIdx.x * 32;
    for (int u = tid; u < 32 * 6; u += 256) {
        int r = u / 6, j = u % 6;
        const uint4* yp = (const uint4*)(g_y4 + (size_t)(n0 + r) * 192 + 32 * j);
        uint4 q0 = yp[0], q1 = yp[1], q2 = yp[2], q3 = yp[3];
        unsigned qq[16] = {q0.x, q0.y, q0.z, q0.w, q1.x, q1.y, q1.z, q1.w,
                           q2.x, q2.y, q2.z, q2.w, q3.x, q3.y, q3.z, q3.w};
        unsigned wd = 0;
#pragma unroll
        for (int b = 0; b < 32; b++) {
            short sv = (short)(qq[b >> 1] >> ((b & 1) * 16));
            int k = 32 * j + b;
            float2 c = s_coef[k >> 1];
            if (fmaf(c.x, (float)sv, c.y) > 0.0f) wd |= 1u << b;
        }
        s_b[u] = wd;
    }
    __syncthreads();
    for (int r = tid; r < 32; r += 256) {
        int p = 0;
#pragma unroll
        for (int j = 0; j < 6; j++) p += __popc(s_b[r * 6 + j]);
        s_pop[r] = p;
    }
    __syncthreads();

    const int o0 = tid;
    const bool has2 = (tid + 256) < 360;
    unsigned w0[6], w1[6];
#pragma unroll
    for (int j = 0; j < 6; j++) w0[j] = s_w[o0 * 6 + j];
    if (has2) {
#pragma unroll
        for (int j = 0; j < 6; j++) w1[j] = s_w[(o0 + 256) * 6 + j];
    }
    float bl0 = s_bl[o0];
    float bl1 = has2 ? s_bl[o0 + 256] : 0.0f;

    if (o0 < 360) {
        for (int r = 0; r < 32; r++) {
            unsigned b0 = s_b[r * 6 + 0], b1 = s_b[r * 6 + 1], b2 = s_b[r * 6 + 2];
            unsigned b3 = s_b[r * 6 + 3], b4 = s_b[r * 6 + 4], b5 = s_b[r * 6 + 5];
            int pop = s_pop[r];
            int a0 = __popc(b0 & w0[0]) + __popc(b1 & w0[1]) + __popc(b2 & w0[2]) +
                     __popc(b3 & w0[3]) + __popc(b4 & w0[4]) + __popc(b5 & w0[5]);
            float* orow = out + (size_t)(n0 + r) * 360;
            orow[o0] = (float)(2 * a0 - pop) + bl0;
            if (has2) {
                int a1 = __popc(b0 & w1[0]) + __popc(b1 & w1[1]) + __popc(b2 & w1[2]) +
                         __popc(b3 & w1[3]) + __popc(b4 & w1[4]) + __popc(b5 & w1[5]);
                orow[o0 + 256] = (float)(2 * a1 - pop) + bl1;
            }
        }
    }
}

// ---------------------------------------------------------------------------
// Launch
// ---------------------------------------------------------------------------
extern "C" void kernel_launch(void* const* d_in, const int* in_sizes, int n_in,
                              void* d_out, int out_size) {
    const float* x   = (const float*)d_in[0];
    const float* w1  = (const float*)d_in[1];
    const float* g1  = (const float*)d_in[3];
    const float* be1 = (const float*)d_in[4];
    const float* w2  = (const float*)d_in[5];
    const float* g2  = (const float*)d_in[7];
    const float* be2 = (const float*)d_in[8];
    const float* w3  = (const float*)d_in[9];
    const float* g3  = (const float*)d_in[11];
    const float* be3 = (const float*)d_in[12];
    const float* w4  = (const float*)d_in[13];
    const float* g4  = (const float*)d_in[15];
    const float* be4 = (const float*)d_in[16];
    const float* wl  = (const float*)d_in[17];
    const float* bl  = (const float*)d_in[18];
    float* out = (float*)d_out;

    prep_kernel<<<64, 256>>>(w1, w2, w3, w4, wl);

    conv1_kernel<<<BATCH / 2, 256>>>(x);
    stats_kernel<1, 12, false><<<1024, 192>>>(BATCH * 345 * 12 / 2);

    conv_rest<2, 12, 15, 23, 24, 7, 11, 16, 1, false>
        <<<BATCH / 16, 256>>>(g1, be1, 1.0 / ((double)BATCH * 345));
    stats_kernel<2, 24, false><<<1024, 192>>>(BATCH * 77 * 24 / 2);

    conv_rest<3, 24, 7, 11, 48, 3, 5, 16, 1, false>
        <<<BATCH / 16, 256>>>(g2, be2, 1.0 / ((double)BATCH * 77));
    stats_kernel<3, 48, false><<<512, 192>>>(BATCH * 15 * 48 / 2);

    conv_rest<4, 48, 3, 5, 96, 1, 2, 16, 8, true>
        <<<BATCH / 16, 256>>>(g3, be3, 1.0 / ((double)BATCH * 15));
    stats_kernel<4, 96, true><<<256, 192>>>(BATCH * 192 / 2);

    linear_kernel<<<BATCH / 32, 256>>>(g4, be4, bl, out);
}

// round 7
// speedup vs baseline: 1.0249x; 1.0249x over previous
#include <cuda_runtime.h>

#define DINL __device__ __forceinline__
typedef unsigned long long ull;

constexpr int BATCH = 8192;

// channel-last activations: (n, pix, ci), except y4 which is (n, co, pix)
__device__ short g_y1[(size_t)BATCH * 345 * 12];
__device__ short g_y2[(size_t)BATCH * 77 * 24];
__device__ short g_y3[(size_t)BATCH * 15 * 48];
__device__ short g_y4[(size_t)BATCH * 192];

__device__ ull g_sum[512];   // layer l at offset l*128
__device__ ull g_sq[512];

__device__ unsigned g_wp1[12 * 5 * 1];
__device__ unsigned g_wp2[24 * 5 * 2];
__device__ unsigned g_wp3[48 * 5 * 4];
__device__ unsigned g_wp4[96 * 5 * 8];
__device__ unsigned g_wlp[360 * 6];

template <int WIDTH>
DINL unsigned wmask_w(int j) {
    int rem = WIDTH - 32 * j;
    return (rem >= 32) ? 0xFFFFFFFFu : ((1u << rem) - 1u);
}

DINL float2 bn_coef(int layer, int c, double invN,
                    const float* __restrict__ g, const float* __restrict__ be) {
    long long S = (long long)g_sum[layer * 128 + c];
    long long Q = (long long)g_sq[layer * 128 + c];
    double m = (double)S * invN;
    double v = (double)Q * invN - m * m;
    double a = (double)g[c] / sqrt(v + 1e-5);
    return make_float2((float)a, (float)((double)be[c] - m * a));
}

// ---------------------------------------------------------------------------
// Prep
// ---------------------------------------------------------------------------
template <int CI, int CO>
DINL void pack_w(const float* __restrict__ w, unsigned* __restrict__ outw,
                 int gtid, int gsz) {
    constexpr int NW = (5 * CI + 31) / 32;
    const int tot = CO * 5 * NW;
    for (int u = gtid; u < tot; u += gsz) {
        int co = u / (5 * NW);
        int kh = (u / NW) % 5;
        int j = u % NW;
        unsigned wd = 0;
        for (int b = 0; b < 32; b++) {
            int t = 32 * j + b;
            if (t < 5 * CI) {
                int kw = t / CI, ci = t % CI;
                if (w[((co * CI + ci) * 5 + kh) * 5 + kw] > 0.0f) wd |= 1u << b;
            }
        }
        outw[u] = wd;
    }
}

__global__ void prep_kernel(const float* __restrict__ w1, const float* __restrict__ w2,
                            const float* __restrict__ w3, const float* __restrict__ w4,
                            const float* __restrict__ wl) {
    int gtid = blockIdx.x * blockDim.x + threadIdx.x;
    int gsz = gridDim.x * blockDim.x;
    for (int i = gtid; i < 512; i += gsz) { g_sum[i] = 0ull; g_sq[i] = 0ull; }
    pack_w<6, 12>(w1, g_wp1, gtid, gsz);
    pack_w<12, 24>(w2, g_wp2, gtid, gsz);
    pack_w<24, 48>(w3, g_wp3, gtid, gsz);
    pack_w<48, 96>(w4, g_wp4, gtid, gsz);
    for (int u = gtid; u < 360 * 6; u += gsz) {
        int o = u / 6, j = u % 6;
        unsigned wd = 0;
        for (int b = 0; b < 32; b++)
            if (wl[o * 192 + 32 * j + b] > 0.0f) wd |= 1u << b;
        g_wlp[u] = wd;
    }
}

// ---------------------------------------------------------------------------
// BN stats: per-channel integer sum / sumsq over a y buffer.
// blockDim=192 so channel assignment per thread is loop-invariant.
// ---------------------------------------------------------------------------
template <int LAYER, int CO, bool PAIRSAME>
__global__ void __launch_bounds__(192) stats_kernel(int npairs) {
    const short* y;
    if constexpr (LAYER == 1) y = g_y1;
    else if constexpr (LAYER == 2) y = g_y2;
    else if constexpr (LAYER == 3) y = g_y3;
    else y = g_y4;

    __shared__ ull s_sum[CO], s_sq[CO];
    const int tid = threadIdx.x;
    for (int i = tid; i < CO; i += 192) { s_sum[i] = 0ull; s_sq[i] = 0ull; }
    __syncthreads();

    const int gtid = blockIdx.x * 192 + tid;
    const int S = gridDim.x * 192;
    const unsigned* yp = (const unsigned*)y;
    int sum0 = 0, sq0 = 0, sum1 = 0, sq1 = 0;
    for (int p = gtid; p < npairs; p += S) {
        unsigned u = yp[p];
        int a = (int)(short)(u & 0xFFFFu);
        int b = (int)(short)(u >> 16);
        if constexpr (PAIRSAME) {
            sum0 += a + b; sq0 += a * a + b * b;
        } else {
            sum0 += a; sq0 += a * a;
            sum1 += b; sq1 += b * b;
        }
    }
    if constexpr (PAIRSAME) {
        int c0 = gtid % CO;
        atomicAdd(&s_sum[c0], (ull)(long long)sum0);
        atomicAdd(&s_sq[c0], (ull)(long long)sq0);
    } else {
        int c0 = (2 * gtid) % CO;
        atomicAdd(&s_sum[c0], (ull)(long long)sum0);
        atomicAdd(&s_sq[c0], (ull)(long long)sq0);
        atomicAdd(&s_sum[c0 + 1], (ull)(long long)sum1);
        atomicAdd(&s_sq[c0 + 1], (ull)(long long)sq1);
    }
    __syncthreads();
    for (int c = tid; c < CO; c += 192) {
        atomicAdd(&g_sum[(LAYER - 1) * 128 + c], s_sum[c]);
        atomicAdd(&g_sq[(LAYER - 1) * 128 + c], s_sq[c]);
    }
}

// ---------------------------------------------------------------------------
// Layer 1: float input, sign in {-1,+1}, padding via mask popcount.
// ---------------------------------------------------------------------------
__global__ void __launch_bounds__(256) conv1_kernel(const float* __restrict__ x) {
    constexpr int CI = 6, HI = 32, WI = 48, CO = 12, HO = 15, WO = 23;
    constexpr int PIXI = HI * WI, NELEM = CI * PIXI, PIXO = HO * WO;
    constexpr int ROWBITS = (WI + 2) * CI;       // 300
    constexpr int ROWW = (ROWBITS + 31) / 32;    // 10
    constexpr int RWA = ROWW + 2;                // 12
    constexpr int PITCH = 320;
    constexpr int IMGS = 2;
    constexpr int NTASK = IMGS * PIXO;           // 690
    constexpr unsigned MASK30 = (1u << 30) - 1u;

    __shared__ unsigned char s_bits[IMGS * HI * PITCH];   // 20480
    __shared__ unsigned s_rows[IMGS * HI * RWA];          // 3072
    __shared__ unsigned s_wp[CO * 5];
    __shared__ unsigned s_mrow[RWA];

    const int tid = threadIdx.x;
    const int n0 = blockIdx.x * IMGS;

    for (int i = tid; i < CO * 5; i += 256) s_wp[i] = g_wp1[i];
    for (int i = tid; i < RWA; i += 256) {
        unsigned w = 0;
        for (int b = 0; b < 32; b++) {
            int t = 32 * i + b;
            int p = t / CI;
            if (t < ROWBITS && p >= 1 && p <= WI) w |= 1u << b;
        }
        s_mrow[i] = w;
    }
    for (int i = tid; i < IMGS * HI * RWA; i += 256) s_rows[i] = 0;
    {
        uint4 z = make_uint4(0, 0, 0, 0);
        uint4* p = (uint4*)s_bits;
        for (int i = tid; i < IMGS * HI * PITCH / 16; i += 256) p[i] = z;
    }
    __syncthreads();

    // stage: float4 -> {0,1} bytes, channel-last with 6B pad at row start
    const float4* xp4 = (const float4*)(x + (size_t)n0 * NELEM);
    for (int u = tid; u < IMGS * NELEM / 4; u += 256) {
        float4 v = xp4[u];
        int e = 4 * u;
        int m = e / NELEM, er = e % NELEM;
        int ci = er / PIXI, pr = er % PIXI;
        int ih = pr / WI, iw = pr % WI;
        unsigned char* bp = &s_bits[(m * HI + ih) * PITCH + 6 + iw * CI + ci];
        bp[0]      = (unsigned char)(v.x > 0.0f);
        bp[CI]     = (unsigned char)(v.y > 0.0f);
        bp[2 * CI] = (unsigned char)(v.z > 0.0f);
        bp[3 * CI] = (unsigned char)(v.w > 0.0f);
    }
    __syncthreads();

    // pack: 32 bytes -> 32 bits via nibble multiply trick
    for (int u = tid; u < IMGS * HI * ROWW; u += 256) {
        int row = u / ROWW, j = u % ROWW;
        const uint4* bw = (const uint4*)&s_bits[row * PITCH + 32 * j];
        uint4 a = bw[0], b = bw[1];
        unsigned w = 0;
        w |= ((a.x * 0x01020408u) >> 24);
        w |= ((a.y * 0x01020408u) >> 24) << 4;
        w |= ((a.z * 0x01020408u) >> 24) << 8;
        w |= ((a.w * 0x01020408u) >> 24) << 12;
        w |= ((b.x * 0x01020408u) >> 24) << 16;
        w |= ((b.y * 0x01020408u) >> 24) << 20;
        w |= ((b.z * 0x01020408u) >> 24) << 24;
        w |= ((b.w * 0x01020408u) >> 24) << 28;
        s_rows[row * RWA + j] = w;
    }
    __syncthreads();

    for (int t = tid; t < NTASK; t += 256) {
        int m = t / PIXO, pix = t % PIXO;
        int oh = pix / WO, ow = pix % WO;
        int s = 2 * ow * CI, wofs = s >> 5, sh = s & 31;

        unsigned aw[5], mw[5];
        int popA = 0;
#pragma unroll
        for (int kh = 0; kh < 5; kh++) {
            int ih = 2 * oh - 1 + kh;
            bool v = (ih >= 0 && ih < HI);
            const unsigned* rw = &s_rows[(m * HI + (v ? ih : 0)) * RWA + wofs];
            aw[kh] = __funnelshift_r(rw[0], rw[1], sh) & MASK30;
            unsigned mm = __funnelshift_r(s_mrow[wofs], s_mrow[wofs + 1], sh) & MASK30;
            mw[kh] = v ? mm : 0u;
            popA += __popc(mw[kh]);
        }
        unsigned* dst = (unsigned*)(g_y1 + ((size_t)(n0 + m) * PIXO + pix) * CO);
#pragma unroll
        for (int cp = 0; cp < CO / 2; cp++) {
            const unsigned* w0 = &s_wp[(2 * cp) * 5];
            const unsigned* w1 = &s_wp[(2 * cp + 1) * 5];
            int a0 = 0, a1 = 0;
#pragma unroll
            for (int kh = 0; kh < 5; kh++) {
                a0 += __popc(mw[kh] & ~(aw[kh] ^ w0[kh]));
                a1 += __popc(mw[kh] & ~(aw[kh] ^ w1[kh]));
            }
            int d0 = 2 * a0 - popA, d1 = 2 * a1 - popA;
            dst[cp] = ((unsigned)d0 & 0xFFFFu) | ((unsigned)d1 << 16);
        }
    }
}

// ---------------------------------------------------------------------------
// Layers 2-4: pairwise channel compute + immediate 32-bit store (low regs).
// Grids sized for high occupancy: blocks >= ~2000 where possible.
// ---------------------------------------------------------------------------
template <int LAYER, int CI, int HI, int WI, int CO, int HO, int WO,
          int IMGS, int COSPLIT, bool COMAJOR>
__global__ void __launch_bounds__(256, 6) conv_rest(const float* __restrict__ gprev,
                                                    const float* __restrict__ beprev,
                                                    double invN) {
    constexpr int PIXI = HI * WI, PIXO = HO * WO;
    constexpr int ROWBITS = (WI + 2) * CI;
    constexpr int ROWW = (ROWBITS + 31) / 32;
    constexpr int NW = (5 * CI + 31) / 32;
    constexpr int RWA = ROWW + NW + 1;
    constexpr int COQ = CO / COSPLIT;
    constexpr int NTASK = IMGS * PIXO * COSPLIT;
    constexpr int WIDTH = 5 * CI;
    constexpr int CREP = CI + 32;

    __shared__ unsigned s_rows[IMGS * HI * RWA];
    __shared__ unsigned s_wp[CO * 5 * NW];
    __shared__ float2 s_crep[CREP];

    const int tid = threadIdx.x;
    const int n0 = blockIdx.x * IMGS;

    const short* yin = nullptr;
    short* yout = nullptr;
    const unsigned* wpg = nullptr;
    if constexpr (LAYER == 2) { yin = g_y1; yout = g_y2; wpg = g_wp2; }
    if constexpr (LAYER == 3) { yin = g_y2; yout = g_y3; wpg = g_wp3; }
    if constexpr (LAYER == 4) { yin = g_y3; yout = g_y4; wpg = g_wp4; }

    for (int i = tid; i < CO * 5 * NW; i += 256) s_wp[i] = wpg[i];
    for (int i = tid; i < IMGS * HI * RWA; i += 256) s_rows[i] = 0;
    if (tid < CI) {
        float2 cf = bn_coef(LAYER - 2, tid, invN, gprev, beprev);
        for (int r = tid; r < CREP; r += CI) s_crep[r] = cf;
    }
    __syncthreads();

    // pack: binarize directly from channel-last gmem (contiguous 32 shorts/word)
    for (int u = tid; u < IMGS * HI * ROWW; u += 256) {
        int row = u / ROWW, j = u % ROWW;
        int m = row / HI, r = row % HI;
        const short* yrow = yin + ((size_t)(n0 + m) * PIXI + r * WI) * CI;
        int mo0 = 32 * j - CI;
        int ci0 = (32 * j) % CI;
        unsigned w = 0;
        if (mo0 >= 0 && mo0 + 32 <= WI * CI) {
            const uint2* p = (const uint2*)(yrow + mo0);
            uint2 q[8];
#pragma unroll
            for (int k2 = 0; k2 < 8; k2++) q[k2] = p[k2];
#pragma unroll
            for (int b = 0; b < 32; b++) {
                unsigned raw = (b & 2) ? q[b >> 2].y : q[b >> 2].x;
                short sv = (short)(raw >> ((b & 1) * 16));
                float2 c = s_crep[ci0 + b];
                if (fmaf(c.x, (float)sv, c.y) > 0.0f) w |= 1u << b;
            }
        } else {
#pragma unroll
            for (int b = 0; b < 32; b++) {
                int mo = mo0 + b;
                if (mo >= 0 && mo < WI * CI) {
                    float2 c = s_crep[ci0 + b];
                    short sv = yrow[mo];
                    if (fmaf(c.x, (float)sv, c.y) > 0.0f) w |= 1u << b;
                }
            }
        }
        s_rows[row * RWA + j] = w;
    }
    __syncthreads();

    for (int t = tid; t < NTASK; t += 256) {
        int coq, pt;
        if constexpr (COSPLIT > 1) {
            coq = t / (IMGS * PIXO);
            pt = t % (IMGS * PIXO);
        } else { coq = 0; pt = t; }
        int m = pt / PIXO, pix = pt % PIXO;
        int oh = pix / WO, ow = pix % WO;
        int s = 2 * ow * CI, wofs = s >> 5, sh = s & 31;

        unsigned aw[5][NW];
        int popA = 0;
#pragma unroll
        for (int kh = 0; kh < 5; kh++) {
            int ih = 2 * oh - 1 + kh;
            bool v = (ih >= 0 && ih < HI);
            const unsigned* rw = &s_rows[(m * HI + (v ? ih : 0)) * RWA + wofs];
#pragma unroll
            for (int j = 0; j < NW; j++) {
                unsigned msk = wmask_w<WIDTH>(j);
                unsigned win = __funnelshift_r(rw[j], rw[j + 1], sh) & msk;
                aw[kh][j] = v ? win : 0u;
                popA += __popc(aw[kh][j]);
            }
        }
        if constexpr (COMAJOR) {
            short* dst = yout + (size_t)(n0 + m) * (CO * PIXO) + pix;
#pragma unroll
            for (int cp = 0; cp < COQ; cp++) {
                int co = coq * COQ + cp;
                const unsigned* wpc = &s_wp[co * 5 * NW];
                int acc = 0;
#pragma unroll
                for (int kh = 0; kh < 5; kh++)
#pragma unroll
                    for (int j = 0; j < NW; j++)
                        acc += __popc(aw[kh][j] & wpc[kh * NW + j]);
                dst[co * PIXO] = (short)(2 * acc - popA);
            }
        } else {
            unsigned* dst = (unsigned*)(yout + ((size_t)(n0 + m) * PIXO + pix) * CO);
#pragma unroll
            for (int cp = 0; cp < COQ / 2; cp++) {
                int co = coq * COQ + 2 * cp;
                const unsigned* w0 = &s_wp[co * 5 * NW];
                const unsigned* w1 = &s_wp[(co + 1) * 5 * NW];
                int a0 = 0, a1 = 0;
#pragma unroll
                for (int kh = 0; kh < 5; kh++)
#pragma unroll
                    for (int j = 0; j < NW; j++) {
                        a0 += __popc(aw[kh][j] & w0[kh * NW + j]);
                        a1 += __popc(aw[kh][j] & w1[kh * NW + j]);
                    }
                int d0 = 2 * a0 - popA, d1 = 2 * a1 - popA;
                dst[coq * COQ / 2 + cp] = ((unsigned)d0 & 0xFFFFu) | ((unsigned)d1 << 16);
            }
        }
    }
}

// ---------------------------------------------------------------------------
// Final binary linear: weights register-resident, rows broadcast from smem.
// ---------------------------------------------------------------------------
__global__ void __launch_bounds__(256) linear_kernel(const float* __restrict__ g4,
                                                     const float* __restrict__ be4,
                                                     const float* __restrict__ bl,
                                                     float* __restrict__ out) {
    __shared__ unsigned s_w[360 * 6];
    __shared__ unsigned s_b[32 * 6];
    __shared__ int s_pop[32];
    __shared__ float s_bl[360];
    __shared__ float2 s_coef[96];

    int tid = threadIdx.x;
    for (int i = tid; i < 360 * 6; i += 256) s_w[i] = g_wlp[i];
    for (int i = tid; i < 360; i += 256) s_bl[i] = bl[i];
    if (tid < 96) s_coef[tid] = bn_coef(3, tid, 1.0 / ((double)BATCH * 2), g4, be4);
    __syncthreads();

    int n0 = blockIdx.x * 32;
    for (int u = tid; u < 32 * 6; u += 256) {
        int r = u / 6, j = u % 6;
        const uint4* yp = (const uint4*)(g_y4 + (size_t)(n0 + r) * 192 + 32 * j);
        uint4 q0 = yp[0], q1 = yp[1], q2 = yp[2], q3 = yp[3];
        unsigned qq[16] = {q0.x, q0.y, q0.z, q0.w, q1.x, q1.y, q1.z, q1.w,
                           q2.x, q2.y, q2.z, q2.w, q3.x, q3.y, q3.z, q3.w};
        unsigned wd = 0;
#pragma unroll
        for (int b = 0; b < 32; b++) {
            short sv = (short)(qq[b >> 1] >> ((b & 1) * 16));
            int k = 32 * j + b;
            float2 c = s_coef[k >> 1];
            if (fmaf(c.x, (float)sv, c.y) > 0.0f) wd |= 1u << b;
        }
        s_b[u] = wd;
    }
    __syncthreads();
    for (int r = tid; r < 32; r += 256) {
        int p = 0;
#pragma unroll
        for (int j = 0; j < 6; j++) p += __popc(s_b[r * 6 + j]);
        s_pop[r] = p;
    }
    __syncthreads();

    const int o0 = tid;
    const bool has2 = (tid + 256) < 360;
    unsigned w0[6], w1[6];
#pragma unroll
    for (int j = 0; j < 6; j++) w0[j] = s_w[o0 * 6 + j];
    if (has2) {
#pragma unroll
        for (int j = 0; j < 6; j++) w1[j] = s_w[(o0 + 256) * 6 + j];
    }
    float bl0 = s_bl[o0];
    float bl1 = has2 ? s_bl[o0 + 256] : 0.0f;

    if (o0 < 360) {
        for (int r = 0; r < 32; r++) {
            unsigned b0 = s_b[r * 6 + 0], b1 = s_b[r * 6 + 1], b2 = s_b[r * 6 + 2];
            unsigned b3 = s_b[r * 6 + 3], b4 = s_b[r * 6 + 4], b5 = s_b[r * 6 + 5];
            int pop = s_pop[r];
            int a0 = __popc(b0 & w0[0]) + __popc(b1 & w0[1]) + __popc(b2 & w0[2]) +
                     __popc(b3 & w0[3]) + __popc(b4 & w0[4]) + __popc(b5 & w0[5]);
            float* orow = out + (size_t)(n0 + r) * 360;
            orow[o0] = (float)(2 * a0 - pop) + bl0;
            if (has2) {
                int a1 = __popc(b0 & w1[0]) + __popc(b1 & w1[1]) + __popc(b2 & w1[2]) +
                         __popc(b3 & w1[3]) + __popc(b4 & w1[4]) + __popc(b5 & w1[5]);
                orow[o0 + 256] = (float)(2 * a1 - pop) + bl1;
            }
        }
    }
}

// ---------------------------------------------------------------------------
// Launch
// ---------------------------------------------------------------------------
extern "C" void kernel_launch(void* const* d_in, const int* in_sizes, int n_in,
                              void* d_out, int out_size) {
    const float* x   = (const float*)d_in[0];
    const float* w1  = (const float*)d_in[1];
    const float* g1  = (const float*)d_in[3];
    const float* be1 = (const float*)d_in[4];
    const float* w2  = (const float*)d_in[5];
    const float* g2  = (const float*)d_in[7];
    const float* be2 = (const float*)d_in[8];
    const float* w3  = (const float*)d_in[9];
    const float* g3  = (const float*)d_in[11];
    const float* be3 = (const float*)d_in[12];
    const float* w4  = (const float*)d_in[13];
    const float* g4  = (const float*)d_in[15];
    const float* be4 = (const float*)d_in[16];
    const float* wl  = (const float*)d_in[17];
    const float* bl  = (const float*)d_in[18];
    float* out = (float*)d_out;

    prep_kernel<<<64, 256>>>(w1, w2, w3, w4, wl);

    conv1_kernel<<<BATCH / 2, 256>>>(x);
    stats_kernel<1, 12, false><<<1024, 192>>>(BATCH * 345 * 12 / 2);

    conv_rest<2, 12, 15, 23, 24, 7, 11, 4, 2, false>
        <<<BATCH / 4, 256>>>(g1, be1, 1.0 / ((double)BATCH * 345));
    stats_kernel<2, 24, false><<<1024, 192>>>(BATCH * 77 * 24 / 2);

    conv_rest<3, 24, 7, 11, 48, 3, 5, 4, 4, false>
        <<<BATCH / 4, 256>>>(g2, be2, 1.0 / ((double)BATCH * 77));
    stats_kernel<3, 48, false><<<512, 192>>>(BATCH * 15 * 48 / 2);

    conv_rest<4, 48, 3, 5, 96, 1, 2, 8, 16, true>
        <<<BATCH / 8, 256>>>(g3, be3, 1.0 / ((double)BATCH * 15));
    stats_kernel<4, 96, true><<<256, 192>>>(BATCH * 192 / 2);

    linear_kernel<<<BATCH / 32, 256>>>(g4, be4, bl, out);
}

// round 8
// speedup vs baseline: 1.3123x; 1.2803x over previous
#include <cuda_runtime.h>

#define DINL __device__ __forceinline__
typedef unsigned long long ull;

constexpr int BATCH = 8192;

// channel-last activations: (n, pix, ci), except y4 which is (n, co, pix)
__device__ short g_y1[(size_t)BATCH * 345 * 12];
__device__ short g_y2[(size_t)BATCH * 77 * 24];
__device__ short g_y3[(size_t)BATCH * 15 * 48];
__device__ short g_y4[(size_t)BATCH * 192];

__device__ ull g_sum[512];   // layer l at offset l*128
__device__ ull g_sq[512];

// weight packs: conv1 as uint2 channel-pairs, conv2-4 as uint4 channel-pairs
// uint4 layout index ((p*5 + kh)*(NW/2) + jj), word = (w0[2jj], w1[2jj], w0[2jj+1], w1[2jj+1])
__device__ uint2 g_wp1[6 * 5];
__device__ uint4 g_wp2[12 * 5 * 1];
__device__ uint4 g_wp3[24 * 5 * 2];
__device__ uint4 g_wp4[48 * 5 * 4];
__device__ unsigned g_wlp[360 * 6];

template <int WIDTH>
DINL unsigned wmask_w(int j) {
    int rem = WIDTH - 32 * j;
    return (rem >= 32) ? 0xFFFFFFFFu : ((1u << rem) - 1u);
}

DINL float2 bn_coef(int layer, int c, double invN,
                    const float* __restrict__ g, const float* __restrict__ be) {
    long long S = (long long)g_sum[layer * 128 + c];
    long long Q = (long long)g_sq[layer * 128 + c];
    double m = (double)S * invN;
    double v = (double)Q * invN - m * m;
    double a = (double)g[c] / sqrt(v + 1e-5);
    return make_float2((float)a, (float)((double)be[c] - m * a));
}

// ---------------------------------------------------------------------------
// Prep: pack weight sign bits (bit t of (co,kh) word j: t=32j+b -> kw=t/CI, ci=t%CI)
// ---------------------------------------------------------------------------
template <int CI>
DINL unsigned sign_word(const float* __restrict__ w, int co, int kh, int j) {
    unsigned wd = 0;
    for (int b = 0; b < 32; b++) {
        int t = 32 * j + b;
        if (t < 5 * CI) {
            int kw = t / CI, ci = t % CI;
            if (w[((co * CI + ci) * 5 + kh) * 5 + kw] > 0.0f) wd |= 1u << b;
        }
    }
    return wd;
}

template <int CI, int CO>
DINL void pack_w4(const float* __restrict__ w, uint4* __restrict__ outw,
                  int gtid, int gsz) {
    constexpr int NW = (5 * CI + 31) / 32;
    constexpr int NH = NW / 2;
    const int tot = (CO / 2) * 5 * NH;
    for (int u = gtid; u < tot; u += gsz) {
        int jj = u % NH;
        int kh = (u / NH) % 5;
        int p = u / (NH * 5);
        uint4 q;
        q.x = sign_word<CI>(w, 2 * p,     kh, 2 * jj);
        q.y = sign_word<CI>(w, 2 * p + 1, kh, 2 * jj);
        q.z = sign_word<CI>(w, 2 * p,     kh, 2 * jj + 1);
        q.w = sign_word<CI>(w, 2 * p + 1, kh, 2 * jj + 1);
        outw[u] = q;
    }
}

__global__ void prep_kernel(const float* __restrict__ w1, const float* __restrict__ w2,
                            const float* __restrict__ w3, const float* __restrict__ w4,
                            const float* __restrict__ wl) {
    int gtid = blockIdx.x * blockDim.x + threadIdx.x;
    int gsz = gridDim.x * blockDim.x;
    for (int i = gtid; i < 512; i += gsz) { g_sum[i] = 0ull; g_sq[i] = 0ull; }
    // conv1: uint2 pairs
    for (int u = gtid; u < 6 * 5; u += gsz) {
        int kh = u % 5, p = u / 5;
        uint2 q;
        q.x = sign_word<6>(w1, 2 * p, kh, 0);
        q.y = sign_word<6>(w1, 2 * p + 1, kh, 0);
        g_wp1[u] = q;
    }
    pack_w4<12, 24>(w2, g_wp2, gtid, gsz);
    pack_w4<24, 48>(w3, g_wp3, gtid, gsz);
    pack_w4<48, 96>(w4, g_wp4, gtid, gsz);
    for (int u = gtid; u < 360 * 6; u += gsz) {
        int o = u / 6, j = u % 6;
        unsigned wd = 0;
        for (int b = 0; b < 32; b++)
            if (wl[o * 192 + 32 * j + b] > 0.0f) wd |= 1u << b;
        g_wlp[u] = wd;
    }
}

// ---------------------------------------------------------------------------
// BN stats: per-channel integer sum / sumsq over a y buffer.
// ---------------------------------------------------------------------------
template <int LAYER, int CO, bool PAIRSAME>
__global__ void __launch_bounds__(192) stats_kernel(int npairs) {
    const short* y;
    if constexpr (LAYER == 1) y = g_y1;
    else if constexpr (LAYER == 2) y = g_y2;
    else if constexpr (LAYER == 3) y = g_y3;
    else y = g_y4;

    __shared__ ull s_sum[CO], s_sq[CO];
    const int tid = threadIdx.x;
    for (int i = tid; i < CO; i += 192) { s_sum[i] = 0ull; s_sq[i] = 0ull; }
    __syncthreads();

    const int gtid = blockIdx.x * 192 + tid;
    const int S = gridDim.x * 192;
    const unsigned* yp = (const unsigned*)y;
    int sum0 = 0, sq0 = 0, sum1 = 0, sq1 = 0;
    for (int p = gtid; p < npairs; p += S) {
        unsigned u = yp[p];
        int a = (int)(short)(u & 0xFFFFu);
        int b = (int)(short)(u >> 16);
        if constexpr (PAIRSAME) {
            sum0 += a + b; sq0 += a * a + b * b;
        } else {
            sum0 += a; sq0 += a * a;
            sum1 += b; sq1 += b * b;
        }
    }
    if constexpr (PAIRSAME) {
        int c0 = gtid % CO;
        atomicAdd(&s_sum[c0], (ull)(long long)sum0);
        atomicAdd(&s_sq[c0], (ull)(long long)sq0);
    } else {
        int c0 = (2 * gtid) % CO;
        atomicAdd(&s_sum[c0], (ull)(long long)sum0);
        atomicAdd(&s_sq[c0], (ull)(long long)sq0);
        atomicAdd(&s_sum[c0 + 1], (ull)(long long)sum1);
        atomicAdd(&s_sq[c0 + 1], (ull)(long long)sq1);
    }
    __syncthreads();
    for (int c = tid; c < CO; c += 192) {
        atomicAdd(&g_sum[(LAYER - 1) * 128 + c], s_sum[c]);
        atomicAdd(&g_sq[(LAYER - 1) * 128 + c], s_sq[c]);
    }
}

// ---------------------------------------------------------------------------
// Layer 1: float input, sign in {-1,+1}, padding via mask popcount.
// ---------------------------------------------------------------------------
__global__ void __launch_bounds__(256) conv1_kernel(const float* __restrict__ x) {
    constexpr int CI = 6, HI = 32, WI = 48, CO = 12, HO = 15, WO = 23;
    constexpr int PIXI = HI * WI, NELEM = CI * PIXI, PIXO = HO * WO;
    constexpr int ROWBITS = (WI + 2) * CI;       // 300
    constexpr int ROWW = (ROWBITS + 31) / 32;    // 10
    constexpr int RWA = ROWW + 2;                // 12
    constexpr int PITCH = 320;
    constexpr int IMGS = 2;
    constexpr int NTASK = IMGS * PIXO;           // 690
    constexpr unsigned MASK30 = (1u << 30) - 1u;

    __shared__ unsigned char s_bits[IMGS * HI * PITCH];   // 20480
    __shared__ unsigned s_rows[IMGS * HI * RWA];          // 3072
    __shared__ uint2 s_wp[6 * 5];
    __shared__ unsigned s_mrow[RWA];

    const int tid = threadIdx.x;
    const int n0 = blockIdx.x * IMGS;

    for (int i = tid; i < 6 * 5; i += 256) s_wp[i] = g_wp1[i];
    for (int i = tid; i < RWA; i += 256) {
        unsigned w = 0;
        for (int b = 0; b < 32; b++) {
            int t = 32 * i + b;
            int p = t / CI;
            if (t < ROWBITS && p >= 1 && p <= WI) w |= 1u << b;
        }
        s_mrow[i] = w;
    }
    for (int i = tid; i < IMGS * HI * RWA; i += 256) s_rows[i] = 0;
    {
        uint4 z = make_uint4(0, 0, 0, 0);
        uint4* p = (uint4*)s_bits;
        for (int i = tid; i < IMGS * HI * PITCH / 16; i += 256) p[i] = z;
    }
    __syncthreads();

    // stage: float4 -> {0,1} bytes, channel-last with 6B pad at row start
    const float4* xp4 = (const float4*)(x + (size_t)n0 * NELEM);
    for (int u = tid; u < IMGS * NELEM / 4; u += 256) {
        float4 v = xp4[u];
        int e = 4 * u;
        int m = e / NELEM, er = e % NELEM;
        int ci = er / PIXI, pr = er % PIXI;
        int ih = pr / WI, iw = pr % WI;
        unsigned char* bp = &s_bits[(m * HI + ih) * PITCH + 6 + iw * CI + ci];
        bp[0]      = (unsigned char)(v.x > 0.0f);
        bp[CI]     = (unsigned char)(v.y > 0.0f);
        bp[2 * CI] = (unsigned char)(v.z > 0.0f);
        bp[3 * CI] = (unsigned char)(v.w > 0.0f);
    }
    __syncthreads();

    // pack: 32 bytes -> 32 bits via nibble multiply trick
    for (int u = tid; u < IMGS * HI * ROWW; u += 256) {
        int row = u / ROWW, j = u % ROWW;
        const uint4* bw = (const uint4*)&s_bits[row * PITCH + 32 * j];
        uint4 a = bw[0], b = bw[1];
        unsigned w = 0;
        w |= ((a.x * 0x01020408u) >> 24);
        w |= ((a.y * 0x01020408u) >> 24) << 4;
        w |= ((a.z * 0x01020408u) >> 24) << 8;
        w |= ((a.w * 0x01020408u) >> 24) << 12;
        w |= ((b.x * 0x01020408u) >> 24) << 16;
        w |= ((b.y * 0x01020408u) >> 24) << 20;
        w |= ((b.z * 0x01020408u) >> 24) << 24;
        w |= ((b.w * 0x01020408u) >> 24) << 28;
        s_rows[row * RWA + j] = w;
    }
    __syncthreads();

    for (int t = tid; t < NTASK; t += 256) {
        int m = t / PIXO, pix = t % PIXO;
        int oh = pix / WO, ow = pix % WO;
        int s = 2 * ow * CI, wofs = s >> 5, sh = s & 31;

        // pad-mask window is kh-invariant: compute once
        const unsigned mm = __funnelshift_r(s_mrow[wofs], s_mrow[wofs + 1], sh) & MASK30;

        unsigned aw[5], mw[5];
        int popA = 0;
#pragma unroll
        for (int kh = 0; kh < 5; kh++) {
            int ih = 2 * oh - 1 + kh;
            bool v = (ih >= 0 && ih < HI);
            const unsigned* rw = &s_rows[(m * HI + (v ? ih : 0)) * RWA + wofs];
            aw[kh] = __funnelshift_r(rw[0], rw[1], sh) & MASK30;
            mw[kh] = v ? mm : 0u;
            popA += __popc(mw[kh]);
        }
        unsigned* dst = (unsigned*)(g_y1 + ((size_t)(n0 + m) * PIXO + pix) * CO);
#pragma unroll
        for (int cp = 0; cp < CO / 2; cp++) {
            int a0 = 0, a1 = 0;
#pragma unroll
            for (int kh = 0; kh < 5; kh++) {
                uint2 q = s_wp[cp * 5 + kh];
                a0 += __popc(mw[kh] & ~(aw[kh] ^ q.x));
                a1 += __popc(mw[kh] & ~(aw[kh] ^ q.y));
            }
            int d0 = 2 * a0 - popA, d1 = 2 * a1 - popA;
            dst[cp] = ((unsigned)d0 & 0xFFFFu) | ((unsigned)d1 << 16);
        }
    }
}

// ---------------------------------------------------------------------------
// Layers 2-4: pairwise channels via uint4 (LDS.128) weight loads.
// ---------------------------------------------------------------------------
template <int LAYER, int CI, int HI, int WI, int CO, int HO, int WO,
          int IMGS, int COSPLIT, bool COMAJOR>
__global__ void __launch_bounds__(256, 6) conv_rest(const float* __restrict__ gprev,
                                                    const float* __restrict__ beprev,
                                                    double invN) {
    constexpr int PIXI = HI * WI, PIXO = HO * WO;
    constexpr int ROWBITS = (WI + 2) * CI;
    constexpr int ROWW = (ROWBITS + 31) / 32;
    constexpr int NW = (5 * CI + 31) / 32;
    static_assert(NW % 2 == 0, "NW even");
    constexpr int NH = NW / 2;
    constexpr int RWA = ROWW + NW + 1;
    constexpr int COQ = CO / COSPLIT;
    static_assert(COQ % 2 == 0, "COQ even");
    constexpr int NTASK = IMGS * PIXO * COSPLIT;
    constexpr int WIDTH = 5 * CI;
    constexpr int CREP = CI + 32;

    __shared__ unsigned s_rows[IMGS * HI * RWA];
    __shared__ uint4 s_wp[(CO / 2) * 5 * NH];
    __shared__ float2 s_crep[CREP];

    const int tid = threadIdx.x;
    const int n0 = blockIdx.x * IMGS;

    const short* yin = nullptr;
    short* yout = nullptr;
    const uint4* wpg = nullptr;
    if constexpr (LAYER == 2) { yin = g_y1; yout = g_y2; wpg = g_wp2; }
    if constexpr (LAYER == 3) { yin = g_y2; yout = g_y3; wpg = g_wp3; }
    if constexpr (LAYER == 4) { yin = g_y3; yout = g_y4; wpg = g_wp4; }

    for (int i = tid; i < (CO / 2) * 5 * NH; i += 256) s_wp[i] = wpg[i];
    for (int i = tid; i < IMGS * HI * RWA; i += 256) s_rows[i] = 0;
    if (tid < CI) {
        float2 cf = bn_coef(LAYER - 2, tid, invN, gprev, beprev);
        for (int r = tid; r < CREP; r += CI) s_crep[r] = cf;
    }
    __syncthreads();

    // pack: binarize directly from channel-last gmem (contiguous 32 shorts/word)
    for (int u = tid; u < IMGS * HI * ROWW; u += 256) {
        int row = u / ROWW, j = u % ROWW;
        int m = row / HI, r = row % HI;
        const short* yrow = yin + ((size_t)(n0 + m) * PIXI + r * WI) * CI;
        int mo0 = 32 * j - CI;
        int ci0 = (32 * j) % CI;
        unsigned w = 0;
        if (mo0 >= 0 && mo0 + 32 <= WI * CI) {
            const uint2* p = (const uint2*)(yrow + mo0);
            uint2 q[8];
#pragma unroll
            for (int k2 = 0; k2 < 8; k2++) q[k2] = p[k2];
#pragma unroll
            for (int b = 0; b < 32; b++) {
                unsigned raw = (b & 2) ? q[b >> 2].y : q[b >> 2].x;
                short sv = (short)(raw >> ((b & 1) * 16));
                float2 c = s_crep[ci0 + b];
                if (fmaf(c.x, (float)sv, c.y) > 0.0f) w |= 1u << b;
            }
        } else {
#pragma unroll
            for (int b = 0; b < 32; b++) {
                int mo = mo0 + b;
                if (mo >= 0 && mo < WI * CI) {
                    float2 c = s_crep[ci0 + b];
                    short sv = yrow[mo];
                    if (fmaf(c.x, (float)sv, c.y) > 0.0f) w |= 1u << b;
                }
            }
        }
        s_rows[row * RWA + j] = w;
    }
    __syncthreads();

    for (int t = tid; t < NTASK; t += 256) {
        int coq, pt;
        if constexpr (COSPLIT > 1) {
            coq = t / (IMGS * PIXO);
            pt = t % (IMGS * PIXO);
        } else { coq = 0; pt = t; }
        int m = pt / PIXO, pix = pt % PIXO;
        int oh = pix / WO, ow = pix % WO;
        int s = 2 * ow * CI, wofs = s >> 5, sh = s & 31;

        unsigned aw[5][NW];
        int popA = 0;
#pragma unroll
        for (int kh = 0; kh < 5; kh++) {
            int ih = 2 * oh - 1 + kh;
            bool v = (ih >= 0 && ih < HI);
            const unsigned* rw = &s_rows[(m * HI + (v ? ih : 0)) * RWA + wofs];
#pragma unroll
            for (int j = 0; j < NW; j++) {
                unsigned msk = wmask_w<WIDTH>(j);
                unsigned win = __funnelshift_r(rw[j], rw[j + 1], sh) & msk;
                aw[kh][j] = v ? win : 0u;
                popA += __popc(aw[kh][j]);
            }
        }
#pragma unroll
        for (int cp = 0; cp < COQ / 2; cp++) {
            const int p = coq * (COQ / 2) + cp;
            const uint4* wq = &s_wp[p * 5 * NH];
            int a0 = 0, a1 = 0;
#pragma unroll
            for (int kh = 0; kh < 5; kh++)
#pragma unroll
                for (int jj = 0; jj < NH; jj++) {
                    uint4 q = wq[kh * NH + jj];
                    a0 += __popc(aw[kh][2 * jj] & q.x) + __popc(aw[kh][2 * jj + 1] & q.z);
                    a1 += __popc(aw[kh][2 * jj] & q.y) + __popc(aw[kh][2 * jj + 1] & q.w);
                }
            int d0 = 2 * a0 - popA, d1 = 2 * a1 - popA;
            if constexpr (COMAJOR) {
                short* dst = yout + (size_t)(n0 + m) * (CO * PIXO) + pix;
                dst[(2 * p) * PIXO] = (short)d0;
                dst[(2 * p + 1) * PIXO] = (short)d1;
            } else {
                unsigned* dst = (unsigned*)(yout + ((size_t)(n0 + m) * PIXO + pix) * CO);
                dst[p] = ((unsigned)d0 & 0xFFFFu) | ((unsigned)d1 << 16);
            }
        }
    }
}

// ---------------------------------------------------------------------------
// Final binary linear: weights register-resident, rows broadcast from smem.
// ---------------------------------------------------------------------------
__global__ void __launch_bounds__(256) linear_kernel(const float* __restrict__ g4,
                                                     const float* __restrict__ be4,
                                                     const float* __restrict__ bl,
                                                     float* __restrict__ out) {
    __shared__ unsigned s_w[360 * 6];
    __shared__ unsigned s_b[32 * 6];
    __shared__ int s_pop[32];
    __shared__ float s_bl[360];
    __shared__ float2 s_coef[96];

    int tid = threadIdx.x;
    for (int i = tid; i < 360 * 6; i += 256) s_w[i] = g_wlp[i];
    for (int i = tid; i < 360; i += 256) s_bl[i] = bl[i];
    if (tid < 96) s_coef[tid] = bn_coef(3, tid, 1.0 / ((double)BATCH * 2), g4, be4);
    __syncthreads();

    int n0 = blockIdx.x * 32;
    for (int u = tid; u < 32 * 6; u += 256) {
        int r = u / 6, j = u % 6;
        const uint4* yp = (const uint4*)(g_y4 + (size_t)(n0 + r) * 192 + 32 * j);
        uint4 q0 = yp[0], q1 = yp[1], q2 = yp[2], q3 = yp[3];
        unsigned qq[16] = {q0.x, q0.y, q0.z, q0.w, q1.x, q1.y, q1.z, q1.w,
                           q2.x, q2.y, q2.z, q2.w, q3.x, q3.y, q3.z, q3.w};
        unsigned wd = 0;
#pragma unroll
        for (int b = 0; b < 32; b++) {
            short sv = (short)(qq[b >> 1] >> ((b & 1) * 16));
            int k = 32 * j + b;
            float2 c = s_coef[k >> 1];
            if (fmaf(c.x, (float)sv, c.y) > 0.0f) wd |= 1u << b;
        }
        s_b[u] = wd;
    }
    __syncthreads();
    for (int r = tid; r < 32; r += 256) {
        int p = 0;
#pragma unroll
        for (int j = 0; j < 6; j++) p += __popc(s_b[r * 6 + j]);
        s_pop[r] = p;
    }
    __syncthreads();

    const int o0 = tid;
    const bool has2 = (tid + 256) < 360;
    unsigned w0[6], w1[6];
#pragma unroll
    for (int j = 0; j < 6; j++) w0[j] = s_w[o0 * 6 + j];
    if (has2) {
#pragma unroll
        for (int j = 0; j < 6; j++) w1[j] = s_w[(o0 + 256) * 6 + j];
    }
    float bl0 = s_bl[o0];
    float bl1 = has2 ? s_bl[o0 + 256] : 0.0f;

    if (o0 < 360) {
        for (int r = 0; r < 32; r++) {
            unsigned b0 = s_b[r * 6 + 0], b1 = s_b[r * 6 + 1], b2 = s_b[r * 6 + 2];
            unsigned b3 = s_b[r * 6 + 3], b4 = s_b[r * 6 + 4], b5 = s_b[r * 6 + 5];
            int pop = s_pop[r];
            int a0 = __popc(b0 & w0[0]) + __popc(b1 & w0[1]) + __popc(b2 & w0[2]) +
                     __popc(b3 & w0[3]) + __popc(b4 & w0[4]) + __popc(b5 & w0[5]);
            float* orow = out + (size_t)(n0 + r) * 360;
            orow[o0] = (float)(2 * a0 - pop) + bl0;
            if (has2) {
                int a1 = __popc(b0 & w1[0]) + __popc(b1 & w1[1]) + __popc(b2 & w1[2]) +
                         __popc(b3 & w1[3]) + __popc(b4 & w1[4]) + __popc(b5 & w1[5]);
                orow[o0 + 256] = (float)(2 * a1 - pop) + bl1;
            }
        }
    }
}

// ---------------------------------------------------------------------------
// Launch
// ---------------------------------------------------------------------------
extern "C" void kernel_launch(void* const* d_in, const int* in_sizes, int n_in,
                              void* d_out, int out_size) {
    const float* x   = (const float*)d_in[0];
    const float* w1  = (const float*)d_in[1];
    const float* g1  = (const float*)d_in[3];
    const float* be1 = (const float*)d_in[4];
    const float* w2  = (const float*)d_in[5];
    const float* g2  = (const float*)d_in[7];
    const float* be2 = (const float*)d_in[8];
    const float* w3  = (const float*)d_in[9];
    const float* g3  = (const float*)d_in[11];
    const float* be3 = (const float*)d_in[12];
    const float* w4  = (const float*)d_in[13];
    const float* g4  = (const float*)d_in[15];
    const float* be4 = (const float*)d_in[16];
    const float* wl  = (const float*)d_in[17];
    const float* bl  = (const float*)d_in[18];
    float* out = (float*)d_out;

    prep_kernel<<<64, 256>>>(w1, w2, w3, w4, wl);

    conv1_kernel<<<BATCH / 2, 256>>>(x);
    stats_kernel<1, 12, false><<<1024, 192>>>(BATCH * 345 * 12 / 2);

    conv_rest<2, 12, 15, 23, 24, 7, 11, 4, 2, false>
        <<<BATCH / 4, 256>>>(g1, be1, 1.0 / ((double)BATCH * 345));
    stats_kernel<2, 24, false><<<1024, 192>>>(BATCH * 77 * 24 / 2);

    conv_rest<3, 24, 7, 11, 48, 3, 5, 4, 4, false>
        <<<BATCH / 4, 256>>>(g2, be2, 1.0 / ((double)BATCH * 77));
    stats_kernel<3, 48, false><<<512, 192>>>(BATCH * 15 * 48 / 2);

    conv_rest<4, 48, 3, 5, 96, 1, 2, 8, 16, true>
        <<<BATCH / 8, 256>>>(g3, be3, 1.0 / ((double)BATCH * 15));
    stats_kernel<4, 96, true><<<256, 192>>>(BATCH * 192 / 2);

    linear_kernel<<<BATCH / 32, 256>>>(g4, be4, bl, out);
}